// round 11
// baseline (speedup 1.0000x reference)
#include <cuda_runtime.h>
#include <cuda_fp16.h>
#include <cstdint>
#include <cstddef>

// out[4096,4096] = half(x)[4096,4096] @ half(W)^T + half(bias)
// E5M10 RNE quantize == __float2half_rn exactly for these inputs.
// Base sm_103 ISA (no tcgen05): cp.async + ldmatrix + mma.sync HMMA.
// R11: persistent CTAs + atomic tile scheduler (removes 4-wave quantization
//      tail). Mainloop identical to R10 (4 warps, 64x64 warp tile, 3-stage
//      ring, 2 CTAs/SM).

#define ND 4096

static constexpr int BM = 128;
static constexpr int BN = 128;
static constexpr int BK = 64;            // 64 halves = 128 B rows
static constexpr int STAGES = 3;
static constexpr int NTHREADS = 128;     // 4 warps
static constexpr int NTILES = (ND / BM) * (ND / BN);   // 1024
static constexpr int GRID_PERSIST = 304; // 152 SMs x 2 CTAs

static constexpr int A_BYTES = BM * 128;              // 16 KB
static constexpr int B_BYTES = BN * 128;              // 16 KB
static constexpr int STAGE_BYTES = A_BYTES + B_BYTES; // 32 KB
static constexpr int SMEM_BYTES = STAGES * STAGE_BYTES; // 96 KB -> 2 CTAs/SM

// __device__ scratch (no runtime allocation allowed)
__device__ __half g_qA[(size_t)ND * ND];
__device__ __half g_qB[(size_t)ND * ND];
__device__ float  g_qbias[ND];
__device__ unsigned int g_tile_ctr;

// ---------------- helpers ----------------
__device__ __forceinline__ uint32_t smem_u32(const void* p) {
    uint32_t a;
    asm("{ .reg .u64 t; cvta.to.shared.u64 t, %1; cvt.u32.u64 %0, t; }" : "=r"(a) : "l"(p));
    return a;
}

__device__ __forceinline__ void ldmatrix_x4(uint32_t& r0, uint32_t& r1, uint32_t& r2,
                                            uint32_t& r3, uint32_t addr) {
    asm volatile("ldmatrix.sync.aligned.m8n8.x4.shared.b16 {%0,%1,%2,%3}, [%4];"
                 : "=r"(r0), "=r"(r1), "=r"(r2), "=r"(r3) : "r"(addr));
}

__device__ __forceinline__ void mma_16816(float* c, const uint32_t* a,
                                          uint32_t b0, uint32_t b1) {
    asm volatile(
        "mma.sync.aligned.m16n8k16.row.col.f32.f16.f16.f32 "
        "{%0,%1,%2,%3}, {%4,%5,%6,%7}, {%8,%9}, {%0,%1,%2,%3};"
        : "+f"(c[0]), "+f"(c[1]), "+f"(c[2]), "+f"(c[3])
        : "r"(a[0]), "r"(a[1]), "r"(a[2]), "r"(a[3]), "r"(b0), "r"(b1));
}

// ---------------- quantize pass (also resets tile counter) ----------------
__global__ void __launch_bounds__(256) quantize_kernel(
    const float* __restrict__ x, const float* __restrict__ w, const float* __restrict__ b) {
    size_t i = (size_t)blockIdx.x * blockDim.x + threadIdx.x;
    if (i == 0) g_tile_ctr = 0;
    const size_t n4 = (size_t)ND * ND / 4;
    const size_t stride = (size_t)gridDim.x * blockDim.x;
    for (size_t idx = i; idx < 2 * n4; idx += stride) {
        bool isA = idx < n4;
        size_t j = isA ? idx : idx - n4;
        float4 v = isA ? ((const float4*)x)[j] : ((const float4*)w)[j];
        __half2* dst = isA ? (__half2*)g_qA : (__half2*)g_qB;
        dst[2 * j]     = __floats2half2_rn(v.x, v.y);
        dst[2 * j + 1] = __floats2half2_rn(v.z, v.w);
    }
    if (i < ND) g_qbias[i] = __half2float(__float2half_rn(b[i]));
}

// ---------------- GEMM ----------------
// Smem tile layout (A and B identical): row-major, 128 B per row (64 halves),
// 16-byte chunk c stored at (c ^ (row & 7)) — conflict-free for cp.async + ldmatrix.
__device__ __forceinline__ void load_stage(uint32_t stage_base, const __half* Ag,
                                           const __half* Bg, int kbase, int tid) {
#pragma unroll
    for (int i = 0; i < 16; ++i) {
        int c = tid + i * NTHREADS;          // 0..2047
        bool isA = c < 1024;
        int cc = c & 1023;
        int row = cc >> 3;
        int ch = cc & 7;
        uint32_t dst = stage_base + (isA ? 0u : (uint32_t)A_BYTES)
                     + (uint32_t)(row * 128) + (uint32_t)((ch ^ (row & 7)) << 4);
        const __half* src = (isA ? Ag : Bg) + (size_t)row * ND + kbase + ch * 8;
        asm volatile("cp.async.cg.shared.global [%0], [%1], 16;" :: "r"(dst), "l"(src));
    }
    asm volatile("cp.async.commit_group;" ::: "memory");
}

__global__ void __launch_bounds__(NTHREADS, 2)
qgemm_kernel(float* __restrict__ out) {
    extern __shared__ char smem_raw[];
    const uint32_t smem_base = smem_u32(smem_raw);
    __shared__ unsigned int s_tile;

    const int tid = threadIdx.x;
    const int wid = tid >> 5;        // 0..3
    const int lane = tid & 31;

    const int wm = wid & 1;          // 2 warps along M -> 64 rows each
    const int wn = wid >> 1;         // 2 warps along N -> 64 cols each

    // Per-lane ldmatrix address components. XOR term depends only on lane.
    const uint32_t xorv = (uint32_t)(lane & 7);
    uint32_t a_row_off[4];
#pragma unroll
    for (int f = 0; f < 4; ++f)
        a_row_off[f] = (uint32_t)((wm * 64 + f * 16 + (lane & 15)) * 128);
    const uint32_t a_ch_base = (uint32_t)(lane >> 4);
    uint32_t b_row_off[4];
#pragma unroll
    for (int h = 0; h < 4; ++h)
        b_row_off[h] = (uint32_t)((wn * 64 + h * 16 + (lane & 7) + ((lane >> 4) & 1) * 8) * 128);
    const uint32_t b_ch_base = (uint32_t)((lane >> 3) & 1);

    constexpr int NIT = ND / BK;   // 64

    for (;;) {
        if (tid == 0) s_tile = atomicAdd(&g_tile_ctr, 1u);
        __syncthreads();                       // publish s_tile; smem ring idle
        const unsigned int t = s_tile;
        __syncthreads();                       // all read before next overwrite
        if (t >= NTILES) break;

        const int tile_m = (int)(t >> 5);      // consecutive t share tile_m (A reuse)
        const int tile_n = (int)(t & 31);

        const __half* Ag = g_qA + (size_t)tile_m * BM * ND;
        const __half* Bg = g_qB + (size_t)tile_n * BN * ND;

        float acc[4][8][4];
#pragma unroll
        for (int f = 0; f < 4; ++f)
#pragma unroll
            for (int g = 0; g < 8; ++g)
#pragma unroll
                for (int r = 0; r < 4; ++r) acc[f][g][r] = 0.0f;

        // Prologue: 2 stages in flight
        load_stage(smem_base + 0 * STAGE_BYTES, Ag, Bg, 0 * BK, tid);
        load_stage(smem_base + 1 * STAGE_BYTES, Ag, Bg, 1 * BK, tid);

        int buf = 0;
        for (int it = 0; it < NIT; ++it) {
            if (it <= NIT - 2) asm volatile("cp.async.wait_group 1;" ::: "memory");
            else               asm volatile("cp.async.wait_group 0;" ::: "memory");
            __syncthreads();

            // Issue next-stage cp.async into the buffer consumed at it-1.
            const int nl = it + 2;
            if (nl < NIT) {
                int nb = buf + 2; if (nb >= STAGES) nb -= STAGES;
                load_stage(smem_base + (uint32_t)(nb * STAGE_BYTES), Ag, Bg, nl * BK, tid);
            }

            const uint32_t sA = smem_base + (uint32_t)(buf * STAGE_BYTES);
            const uint32_t sB = sA + A_BYTES;

#pragma unroll
            for (int ks = 0; ks < BK / 16; ++ks) {
                uint32_t a[4][4];
#pragma unroll
                for (int f = 0; f < 4; ++f) {
                    uint32_t ch = (uint32_t)(ks * 2) + a_ch_base;
                    ldmatrix_x4(a[f][0], a[f][1], a[f][2], a[f][3],
                                sA + a_row_off[f] + ((ch ^ xorv) << 4));
                }
                uint32_t bfrag[4][4];
#pragma unroll
                for (int h = 0; h < 4; ++h) {
                    uint32_t ch = (uint32_t)(ks * 2) + b_ch_base;
                    ldmatrix_x4(bfrag[h][0], bfrag[h][1], bfrag[h][2], bfrag[h][3],
                                sB + b_row_off[h] + ((ch ^ xorv) << 4));
                }
#pragma unroll
                for (int f = 0; f < 4; ++f)
#pragma unroll
                    for (int g = 0; g < 8; ++g)
                        mma_16816(acc[f][g], a[f], bfrag[g >> 1][(g & 1) * 2],
                                  bfrag[g >> 1][(g & 1) * 2 + 1]);
            }

            if (++buf == STAGES) buf = 0;
        }

        // ---------------- epilogue ----------------
        const int row_base = tile_m * BM + wm * 64 + (lane >> 2);
        const int col_base = tile_n * BN + wn * 64 + 2 * (lane & 3);
#pragma unroll
        for (int f = 0; f < 4; ++f) {
#pragma unroll
            for (int g = 0; g < 8; ++g) {
                const int col = col_base + g * 8;
                const float2 bv = *(const float2*)(g_qbias + col);
                const int r0 = row_base + f * 16;
                float2 v0, v1;
                v0.x = acc[f][g][0] + bv.x;  v0.y = acc[f][g][1] + bv.y;
                v1.x = acc[f][g][2] + bv.x;  v1.y = acc[f][g][3] + bv.y;
                *(float2*)(out + (size_t)r0 * ND + col) = v0;
                *(float2*)(out + (size_t)(r0 + 8) * ND + col) = v1;
            }
        }
    }
}

// ---------------- launch ----------------
extern "C" void kernel_launch(void* const* d_in, const int* in_sizes, int n_in,
                              void* d_out, int out_size) {
    const float* x = (const float*)d_in[0];
    const float* w = (const float*)d_in[1];
    const float* b = (const float*)d_in[2];
    float* out = (float*)d_out;

    quantize_kernel<<<4096, 256>>>(x, w, b);

    cudaFuncSetAttribute(qgemm_kernel, cudaFuncAttributeMaxDynamicSharedMemorySize, SMEM_BYTES);
    qgemm_kernel<<<GRID_PERSIST, NTHREADS, SMEM_BYTES>>>(out);
}

// round 12
// speedup vs baseline: 1.1608x; 1.1608x over previous
#include <cuda_runtime.h>
#include <cuda_fp16.h>
#include <cstdint>
#include <cstddef>

// out[4096,4096] = half(x)[4096,4096] @ half(W)^T + half(bias)
// E5M10 RNE quantize == __float2half_rn exactly for these inputs.
// Base sm_103 ISA (no tcgen05): cp.async + ldmatrix + mma.sync HMMA.
// R12: revert to R10 grid kernel (persistent scheduler regressed). Add
//      intra-stage pipelining: B-frag double buffer + A-frag rotation,
//      immediate-folded LDSM offsets, cp.async issued under the MMA stream.

#define ND 4096

static constexpr int BM = 128;
static constexpr int BN = 128;
static constexpr int BK = 64;            // 64 halves = 128 B rows
static constexpr int STAGES = 3;
static constexpr int NTHREADS = 128;     // 4 warps

static constexpr int A_BYTES = BM * 128;              // 16 KB
static constexpr int B_BYTES = BN * 128;              // 16 KB
static constexpr int STAGE_BYTES = A_BYTES + B_BYTES; // 32 KB
static constexpr int SMEM_BYTES = STAGES * STAGE_BYTES; // 96 KB -> 2 CTAs/SM

// __device__ scratch (no runtime allocation allowed)
__device__ __half g_qA[(size_t)ND * ND];
__device__ __half g_qB[(size_t)ND * ND];
__device__ float  g_qbias[ND];

// ---------------- helpers ----------------
__device__ __forceinline__ uint32_t smem_u32(const void* p) {
    uint32_t a;
    asm("{ .reg .u64 t; cvta.to.shared.u64 t, %1; cvt.u32.u64 %0, t; }" : "=r"(a) : "l"(p));
    return a;
}

__device__ __forceinline__ void ldmatrix_x4(uint32_t& r0, uint32_t& r1, uint32_t& r2,
                                            uint32_t& r3, uint32_t addr) {
    asm volatile("ldmatrix.sync.aligned.m8n8.x4.shared.b16 {%0,%1,%2,%3}, [%4];"
                 : "=r"(r0), "=r"(r1), "=r"(r2), "=r"(r3) : "r"(addr));
}

__device__ __forceinline__ void mma_16816(float* c, const uint32_t* a,
                                          uint32_t b0, uint32_t b1) {
    asm volatile(
        "mma.sync.aligned.m16n8k16.row.col.f32.f16.f16.f32 "
        "{%0,%1,%2,%3}, {%4,%5,%6,%7}, {%8,%9}, {%0,%1,%2,%3};"
        : "+f"(c[0]), "+f"(c[1]), "+f"(c[2]), "+f"(c[3])
        : "r"(a[0]), "r"(a[1]), "r"(a[2]), "r"(a[3]), "r"(b0), "r"(b1));
}

// ---------------- quantize pass ----------------
__global__ void __launch_bounds__(256) quantize_kernel(
    const float* __restrict__ x, const float* __restrict__ w, const float* __restrict__ b) {
    size_t i = (size_t)blockIdx.x * blockDim.x + threadIdx.x;
    const size_t n4 = (size_t)ND * ND / 4;
    const size_t stride = (size_t)gridDim.x * blockDim.x;
    for (size_t idx = i; idx < 2 * n4; idx += stride) {
        bool isA = idx < n4;
        size_t j = isA ? idx : idx - n4;
        float4 v = isA ? ((const float4*)x)[j] : ((const float4*)w)[j];
        __half2* dst = isA ? (__half2*)g_qA : (__half2*)g_qB;
        dst[2 * j]     = __floats2half2_rn(v.x, v.y);
        dst[2 * j + 1] = __floats2half2_rn(v.z, v.w);
    }
    if (i < ND) g_qbias[i] = __half2float(__float2half_rn(b[i]));
}

// ---------------- GEMM ----------------
// Smem tile layout (A and B identical): row-major, 128 B per row (64 halves),
// 16-byte chunk c stored at (c ^ (row & 7)) — conflict-free for cp.async + ldmatrix.
__device__ __forceinline__ void load_stage(uint32_t stage_base, const __half* Ag,
                                           const __half* Bg, int kbase, int tid) {
#pragma unroll
    for (int i = 0; i < 16; ++i) {
        int c = tid + i * NTHREADS;          // 0..2047
        bool isA = c < 1024;
        int cc = c & 1023;
        int row = cc >> 3;
        int ch = cc & 7;
        uint32_t dst = stage_base + (isA ? 0u : (uint32_t)A_BYTES)
                     + (uint32_t)(row * 128) + (uint32_t)((ch ^ (row & 7)) << 4);
        const __half* src = (isA ? Ag : Bg) + (size_t)row * ND + kbase + ch * 8;
        asm volatile("cp.async.cg.shared.global [%0], [%1], 16;" :: "r"(dst), "l"(src));
    }
    asm volatile("cp.async.commit_group;" ::: "memory");
}

__global__ void __launch_bounds__(NTHREADS, 2)
qgemm_kernel(float* __restrict__ out) {
    extern __shared__ char smem_raw[];
    const uint32_t smem_base = smem_u32(smem_raw);

    const int tid = threadIdx.x;
    const int wid = tid >> 5;        // 0..3
    const int lane = tid & 31;
    const int tile_n = blockIdx.x;   // 0..31
    const int tile_m = blockIdx.y;   // 0..31

    const int wm = wid & 1;          // 2 warps along M -> 64 rows each
    const int wn = wid >> 1;         // 2 warps along N -> 64 cols each

    const __half* Ag = g_qA + (size_t)tile_m * BM * ND;
    const __half* Bg = g_qB + (size_t)tile_n * BN * ND;

    // Per-lane base offsets; per-fragment deltas are compile-time immediates
    // (f*2048 / h*2048) folded into the LDSM address in SASS.
    const uint32_t xorv = (uint32_t)(lane & 7);
    const uint32_t a_base = (uint32_t)((wm * 64 + (lane & 15)) * 128);
    const uint32_t a_ch_base = (uint32_t)(lane >> 4);
    const uint32_t b_base =
        (uint32_t)((wn * 64 + (lane & 7) + ((lane >> 4) & 1) * 8) * 128);
    const uint32_t b_ch_base = (uint32_t)((lane >> 3) & 1);

    float acc[4][8][4];
#pragma unroll
    for (int f = 0; f < 4; ++f)
#pragma unroll
        for (int g = 0; g < 8; ++g)
#pragma unroll
            for (int r = 0; r < 4; ++r) acc[f][g][r] = 0.0f;

    uint32_t a[4][4];        // A fragments, rotated in place (reload after last use)
    uint32_t bb[2][4][4];    // B fragments, double-buffered per k-step

    constexpr int NIT = ND / BK;   // 64

    // Prologue: 2 stages in flight
    load_stage(smem_base + 0 * STAGE_BYTES, Ag, Bg, 0 * BK, tid);
    load_stage(smem_base + 1 * STAGE_BYTES, Ag, Bg, 1 * BK, tid);

    int buf = 0;
    for (int it = 0; it < NIT; ++it) {
        if (it <= NIT - 2) asm volatile("cp.async.wait_group 1;" ::: "memory");
        else               asm volatile("cp.async.wait_group 0;" ::: "memory");
        __syncthreads();

        const uint32_t sA = smem_base + (uint32_t)(buf * STAGE_BYTES);
        const uint32_t sB = sA + A_BYTES;

        // ks=0 fragments first so MMAs can start ASAP.
        {
            const uint32_t aoff = sA + a_base + ((a_ch_base ^ xorv) << 4);
#pragma unroll
            for (int f = 0; f < 4; ++f)
                ldmatrix_x4(a[f][0], a[f][1], a[f][2], a[f][3], aoff + f * 2048);
            const uint32_t boff = sB + b_base + ((b_ch_base ^ xorv) << 4);
#pragma unroll
            for (int h = 0; h < 4; ++h)
                ldmatrix_x4(bb[0][h][0], bb[0][h][1], bb[0][h][2], bb[0][h][3],
                            boff + h * 2048);
        }

        // Next-stage cp.async issues overlap the MMA stream below (LSU vs tensor).
        const int nl = it + 2;
        if (nl < NIT) {
            int nb = buf + 2; if (nb >= STAGES) nb -= STAGES;
            load_stage(smem_base + (uint32_t)(nb * STAGE_BYTES), Ag, Bg, nl * BK, tid);
        }

#pragma unroll
        for (int ks = 0; ks < BK / 16; ++ks) {
            const int cb = ks & 1;
            // Prefetch all B fragments for ks+1 into the alternate buffer.
            if (ks < BK / 16 - 1) {
                const uint32_t boff =
                    sB + b_base + ((((uint32_t)((ks + 1) * 2) + b_ch_base) ^ xorv) << 4);
#pragma unroll
                for (int h = 0; h < 4; ++h)
                    ldmatrix_x4(bb[cb ^ 1][h][0], bb[cb ^ 1][h][1], bb[cb ^ 1][h][2],
                                bb[cb ^ 1][h][3], boff + h * 2048);
            }
            const uint32_t aoff_n =
                sA + a_base + ((((uint32_t)((ks + 1) * 2) + a_ch_base) ^ xorv) << 4);
            // f-major MMAs; rotate a[f] for ks+1 right after its last use this step.
#pragma unroll
            for (int f = 0; f < 4; ++f) {
#pragma unroll
                for (int g = 0; g < 8; ++g)
                    mma_16816(acc[f][g], a[f], bb[cb][g >> 1][(g & 1) * 2],
                              bb[cb][g >> 1][(g & 1) * 2 + 1]);
                if (ks < BK / 16 - 1)
                    ldmatrix_x4(a[f][0], a[f][1], a[f][2], a[f][3], aoff_n + f * 2048);
            }
        }

        if (++buf == STAGES) buf = 0;
    }

    // ---------------- epilogue ----------------
    const int row_base = tile_m * BM + wm * 64 + (lane >> 2);
    const int col_base = tile_n * BN + wn * 64 + 2 * (lane & 3);
#pragma unroll
    for (int f = 0; f < 4; ++f) {
#pragma unroll
        for (int g = 0; g < 8; ++g) {
            const int col = col_base + g * 8;
            const float2 bv = *(const float2*)(g_qbias + col);
            const int r0 = row_base + f * 16;
            float2 v0, v1;
            v0.x = acc[f][g][0] + bv.x;  v0.y = acc[f][g][1] + bv.y;
            v1.x = acc[f][g][2] + bv.x;  v1.y = acc[f][g][3] + bv.y;
            *(float2*)(out + (size_t)r0 * ND + col) = v0;
            *(float2*)(out + (size_t)(r0 + 8) * ND + col) = v1;
        }
    }
}

// ---------------- launch ----------------
extern "C" void kernel_launch(void* const* d_in, const int* in_sizes, int n_in,
                              void* d_out, int out_size) {
    const float* x = (const float*)d_in[0];
    const float* w = (const float*)d_in[1];
    const float* b = (const float*)d_in[2];
    float* out = (float*)d_out;

    quantize_kernel<<<4096, 256>>>(x, w, b);

    cudaFuncSetAttribute(qgemm_kernel, cudaFuncAttributeMaxDynamicSharedMemorySize, SMEM_BYTES);
    dim3 grid(ND / BN, ND / BM);   // 32 x 32 = 1024 CTAs
    qgemm_kernel<<<grid, NTHREADS, SMEM_BYTES>>>(out);
}

// round 14
// speedup vs baseline: 1.2265x; 1.0566x over previous
#include <cuda_runtime.h>
#include <cuda_fp16.h>
#include <cstdint>
#include <cstddef>

// out[4096,4096] = half(x)[4096,4096] @ half(W)^T + half(bias)
// E5M10 RNE quantize == __float2half_rn exactly for these inputs.
// Base sm_103 ISA (no tcgen05): cp.async + ldmatrix + mma.sync HMMA.
// R14: R13 with the __half2_as_uint compile fix (union bit-cast).
//      GEMM = exact R10 (best: 295us). Quantize: 16B stores, 8-deep load
//      ILP, streaming (__ldcs) reads, branch-free.

#define ND 4096

static constexpr int BM = 128;
static constexpr int BN = 128;
static constexpr int BK = 64;            // 64 halves = 128 B rows
static constexpr int STAGES = 3;
static constexpr int NTHREADS = 128;     // 4 warps

static constexpr int A_BYTES = BM * 128;              // 16 KB
static constexpr int B_BYTES = BN * 128;              // 16 KB
static constexpr int STAGE_BYTES = A_BYTES + B_BYTES; // 32 KB
static constexpr int SMEM_BYTES = STAGES * STAGE_BYTES; // 96 KB -> 2 CTAs/SM

// __device__ scratch (no runtime allocation allowed)
__device__ __half g_qA[(size_t)ND * ND];
__device__ __half g_qB[(size_t)ND * ND];
__device__ float  g_qbias[ND];

// ---------------- helpers ----------------
__device__ __forceinline__ uint32_t smem_u32(const void* p) {
    uint32_t a;
    asm("{ .reg .u64 t; cvta.to.shared.u64 t, %1; cvt.u32.u64 %0, t; }" : "=r"(a) : "l"(p));
    return a;
}

__device__ __forceinline__ void ldmatrix_x4(uint32_t& r0, uint32_t& r1, uint32_t& r2,
                                            uint32_t& r3, uint32_t addr) {
    asm volatile("ldmatrix.sync.aligned.m8n8.x4.shared.b16 {%0,%1,%2,%3}, [%4];"
                 : "=r"(r0), "=r"(r1), "=r"(r2), "=r"(r3) : "r"(addr));
}

__device__ __forceinline__ void mma_16816(float* c, const uint32_t* a,
                                          uint32_t b0, uint32_t b1) {
    asm volatile(
        "mma.sync.aligned.m16n8k16.row.col.f32.f16.f16.f32 "
        "{%0,%1,%2,%3}, {%4,%5,%6,%7}, {%8,%9}, {%0,%1,%2,%3};"
        : "+f"(c[0]), "+f"(c[1]), "+f"(c[2]), "+f"(c[3])
        : "r"(a[0]), "r"(a[1]), "r"(a[2]), "r"(a[3]), "r"(b0), "r"(b1));
}

// ---------------- quantize pass ----------------
__device__ __forceinline__ uint32_t h2_bits(__half2 h) {
    union { __half2 h; uint32_t u; } cv;
    cv.h = h;
    return cv.u;
}

__device__ __forceinline__ uint4 q8(float4 v0, float4 v1) {
    uint4 o;
    o.x = h2_bits(__floats2half2_rn(v0.x, v0.y));
    o.y = h2_bits(__floats2half2_rn(v0.z, v0.w));
    o.z = h2_bits(__floats2half2_rn(v1.x, v1.y));
    o.w = h2_bits(__floats2half2_rn(v1.z, v1.w));
    return o;
}

// Each thread: 2 groups of 8 floats per array, 8 streaming loads in flight,
// four 16-byte stores.
__global__ void __launch_bounds__(256) quantize_kernel(
    const float* __restrict__ x, const float* __restrict__ w, const float* __restrict__ b) {
    const size_t i = (size_t)blockIdx.x * blockDim.x + threadIdx.x;
    const size_t T = (size_t)gridDim.x * blockDim.x;       // 1,048,576
    const float4* __restrict__ x4 = (const float4*)x;
    const float4* __restrict__ w4 = (const float4*)w;
    uint4* __restrict__ qa4 = (uint4*)g_qA;
    uint4* __restrict__ qb4 = (uint4*)g_qB;

    const size_t j0 = i;        // group 0
    const size_t j1 = i + T;    // group 1
    float4 a0 = __ldcs(&x4[2 * j0]),     a1 = __ldcs(&x4[2 * j0 + 1]);
    float4 a2 = __ldcs(&x4[2 * j1]),     a3 = __ldcs(&x4[2 * j1 + 1]);
    float4 b0 = __ldcs(&w4[2 * j0]),     b1 = __ldcs(&w4[2 * j0 + 1]);
    float4 b2 = __ldcs(&w4[2 * j1]),     b3 = __ldcs(&w4[2 * j1 + 1]);

    qa4[j0] = q8(a0, a1);
    qa4[j1] = q8(a2, a3);
    qb4[j0] = q8(b0, b1);
    qb4[j1] = q8(b2, b3);

    if (i < ND) g_qbias[i] = __half2float(__float2half_rn(b[i]));
}

// ---------------- GEMM (exact R10 mainloop) ----------------
// Smem tile layout (A and B identical): row-major, 128 B per row (64 halves),
// 16-byte chunk c stored at (c ^ (row & 7)) — conflict-free for cp.async + ldmatrix.
__device__ __forceinline__ void load_stage(uint32_t stage_base, const __half* Ag,
                                           const __half* Bg, int kbase, int tid) {
#pragma unroll
    for (int i = 0; i < 16; ++i) {
        int c = tid + i * NTHREADS;          // 0..2047
        bool isA = c < 1024;
        int cc = c & 1023;
        int row = cc >> 3;
        int ch = cc & 7;
        uint32_t dst = stage_base + (isA ? 0u : (uint32_t)A_BYTES)
                     + (uint32_t)(row * 128) + (uint32_t)((ch ^ (row & 7)) << 4);
        const __half* src = (isA ? Ag : Bg) + (size_t)row * ND + kbase + ch * 8;
        asm volatile("cp.async.cg.shared.global [%0], [%1], 16;" :: "r"(dst), "l"(src));
    }
    asm volatile("cp.async.commit_group;" ::: "memory");
}

__global__ void __launch_bounds__(NTHREADS, 2)
qgemm_kernel(float* __restrict__ out) {
    extern __shared__ char smem_raw[];
    const uint32_t smem_base = smem_u32(smem_raw);

    const int tid = threadIdx.x;
    const int wid = tid >> 5;        // 0..3
    const int lane = tid & 31;
    const int tile_n = blockIdx.x;   // 0..31
    const int tile_m = blockIdx.y;   // 0..31

    const int wm = wid & 1;          // 2 warps along M -> 64 rows each
    const int wn = wid >> 1;         // 2 warps along N -> 64 cols each

    const __half* Ag = g_qA + (size_t)tile_m * BM * ND;
    const __half* Bg = g_qB + (size_t)tile_n * BN * ND;

    // Per-lane ldmatrix address components. XOR term depends only on lane.
    const uint32_t xorv = (uint32_t)(lane & 7);
    uint32_t a_row_off[4];
#pragma unroll
    for (int f = 0; f < 4; ++f)
        a_row_off[f] = (uint32_t)((wm * 64 + f * 16 + (lane & 15)) * 128);
    const uint32_t a_ch_base = (uint32_t)(lane >> 4);
    uint32_t b_row_off[4];
#pragma unroll
    for (int h = 0; h < 4; ++h)
        b_row_off[h] = (uint32_t)((wn * 64 + h * 16 + (lane & 7) + ((lane >> 4) & 1) * 8) * 128);
    const uint32_t b_ch_base = (uint32_t)((lane >> 3) & 1);

    float acc[4][8][4];
#pragma unroll
    for (int f = 0; f < 4; ++f)
#pragma unroll
        for (int g = 0; g < 8; ++g)
#pragma unroll
            for (int r = 0; r < 4; ++r) acc[f][g][r] = 0.0f;

    constexpr int NIT = ND / BK;   // 64

    // Prologue: 2 stages in flight
    load_stage(smem_base + 0 * STAGE_BYTES, Ag, Bg, 0 * BK, tid);
    load_stage(smem_base + 1 * STAGE_BYTES, Ag, Bg, 1 * BK, tid);

    int buf = 0;
    for (int it = 0; it < NIT; ++it) {
        if (it <= NIT - 2) asm volatile("cp.async.wait_group 1;" ::: "memory");
        else               asm volatile("cp.async.wait_group 0;" ::: "memory");
        __syncthreads();

        // Issue next-stage cp.async into the buffer consumed at it-1.
        const int nl = it + 2;
        if (nl < NIT) {
            int nb = buf + 2; if (nb >= STAGES) nb -= STAGES;
            load_stage(smem_base + (uint32_t)(nb * STAGE_BYTES), Ag, Bg, nl * BK, tid);
        }

        const uint32_t sA = smem_base + (uint32_t)(buf * STAGE_BYTES);
        const uint32_t sB = sA + A_BYTES;

#pragma unroll
        for (int ks = 0; ks < BK / 16; ++ks) {
            uint32_t a[4][4];
#pragma unroll
            for (int f = 0; f < 4; ++f) {
                uint32_t ch = (uint32_t)(ks * 2) + a_ch_base;
                ldmatrix_x4(a[f][0], a[f][1], a[f][2], a[f][3],
                            sA + a_row_off[f] + ((ch ^ xorv) << 4));
            }
            uint32_t bfrag[4][4];
#pragma unroll
            for (int h = 0; h < 4; ++h) {
                uint32_t ch = (uint32_t)(ks * 2) + b_ch_base;
                ldmatrix_x4(bfrag[h][0], bfrag[h][1], bfrag[h][2], bfrag[h][3],
                            sB + b_row_off[h] + ((ch ^ xorv) << 4));
            }
#pragma unroll
            for (int f = 0; f < 4; ++f)
#pragma unroll
                for (int g = 0; g < 8; ++g)
                    mma_16816(acc[f][g], a[f], bfrag[g >> 1][(g & 1) * 2],
                              bfrag[g >> 1][(g & 1) * 2 + 1]);
        }

        if (++buf == STAGES) buf = 0;
    }

    // ---------------- epilogue ----------------
    const int row_base = tile_m * BM + wm * 64 + (lane >> 2);
    const int col_base = tile_n * BN + wn * 64 + 2 * (lane & 3);
#pragma unroll
    for (int f = 0; f < 4; ++f) {
#pragma unroll
        for (int g = 0; g < 8; ++g) {
            const int col = col_base + g * 8;
            const float2 bv = *(const float2*)(g_qbias + col);
            const int r0 = row_base + f * 16;
            float2 v0, v1;
            v0.x = acc[f][g][0] + bv.x;  v0.y = acc[f][g][1] + bv.y;
            v1.x = acc[f][g][2] + bv.x;  v1.y = acc[f][g][3] + bv.y;
            *(float2*)(out + (size_t)r0 * ND + col) = v0;
            *(float2*)(out + (size_t)(r0 + 8) * ND + col) = v1;
        }
    }
}

// ---------------- launch ----------------
extern "C" void kernel_launch(void* const* d_in, const int* in_sizes, int n_in,
                              void* d_out, int out_size) {
    const float* x = (const float*)d_in[0];
    const float* w = (const float*)d_in[1];
    const float* b = (const float*)d_in[2];
    float* out = (float*)d_out;

    quantize_kernel<<<4096, 256>>>(x, w, b);

    cudaFuncSetAttribute(qgemm_kernel, cudaFuncAttributeMaxDynamicSharedMemorySize, SMEM_BYTES);
    dim3 grid(ND / BN, ND / BM);   // 32 x 32 = 1024 CTAs
    qgemm_kernel<<<grid, NTHREADS, SMEM_BYTES>>>(out);
}